// round 3
// baseline (speedup 1.0000x reference)
#include <cuda_runtime.h>

// Problem constants (fixed by setup_inputs)
#define B       8
#define G       64
#define C       80
#define NLEV    5
#define TOTAL   21824   // 128^2 + 64^2 + 32^2 + 16^2 + 8^2
#define NBG     (B * G)

// Scratch: per-(b,g,level) loss. __device__ global — no allocation.
__device__ float g_losses[NBG * NLEV];

__device__ __forceinline__ float warp_reduce(float v) {
    #pragma unroll
    for (int o = 16; o > 0; o >>= 1)
        v += __shfl_down_sync(0xffffffffu, v, o);
    return v;
}

// One block per (bg, level). Computes loss_cls + loss_iou over the projected
// shrunk-box mask, divided by cell count; BIG if the projection is empty.
__global__ __launch_bounds__(128) void level_loss_kernel(
    const float* __restrict__ cls,    // (B, TOTAL, C)
    const float* __restrict__ regr,   // (B, TOTAL, 4)
    const float* __restrict__ gt)     // (B, G, 5)
{
    // per-level tables
    const int   fw_tab[NLEV]     = {128, 64, 32, 16, 8};
    const int   start_tab[NLEV]  = {0, 16384, 20480, 21504, 21760};
    const float stride_tab[NLEV] = {8.f, 16.f, 32.f, 64.f, 128.f};

    const int unit  = blockIdx.x;       // bg*5 + level
    const int level = unit % NLEV;
    const int bg    = unit / NLEV;
    const int b     = bg / G;

    const float* bx = gt + bg * 5;
    const float b0 = bx[0], b1 = bx[1], b2 = bx[2], b3 = bx[3];

    // invalid (zeroed) box: argmin kernel emits -1, no work needed here
    if (fabsf(b0) + fabsf(b1) + fabsf(b2) + fabsf(b3) == 0.0f) return;

    int label = (int)bx[4];
    label = min(max(label, 0), C - 1);

    const float stride = stride_tab[level];
    const int   fw     = fw_tab[level];
    const int   fh     = fw;
    const int   start  = start_tab[level];

    // projection — replicate reference op order exactly (stride is 2^k → exact division)
    const float cx = (b0 + b2) * 0.5f;
    const float cy = (b1 + b3) * 0.5f;
    const float hw = (b2 - b0) * 0.5f * 0.2f;
    const float hh = (b3 - b1) * 0.5f * 0.2f;

    int x1 = min(max((int)floorf((cx - hw) / stride), 0), fw - 1);
    int y1 = min(max((int)floorf((cy - hh) / stride), 0), fh - 1);
    int x2 = min(max((int)ceilf((cx + hw) / stride), 1), fw);
    int y2 = min(max((int)ceilf((cy + hh) / stride), 1), fh);

    if (x1 == x2 || y1 == y2) {
        if (threadIdx.x == 0) g_losses[unit] = 1e7f;  // BIG
        return;
    }

    const int wid    = x2 - x1;
    const int ncells = wid * (y2 - y1);
    const int work   = ncells * C;

    const long long base_b = (long long)b * TOTAL;
    const float inv4s = 1.0f / (4.0f * stride);

    float acc = 0.0f;

    for (int i = threadIdx.x; i < work; i += blockDim.x) {
        const int cell = i / C;
        const int c    = i - cell * C;
        const int px   = x1 + cell % wid;
        const int py   = y1 + cell / wid;
        const int pos  = start + py * fw + px;
        const long long pidx = base_b + pos;

        float p = cls[pidx * C + c];
        p = fminf(fmaxf(p, 1e-7f), 1.0f - 1e-7f);

        // GAMMA = 2 → powers are plain squares
        const float neg = 0.75f * p * p * (-log1pf(-p));
        acc += neg;

        if (c == label) {
            const float omp = 1.0f - p;
            const float posv = 0.25f * omp * omp * (-logf(p));
            acc += posv - neg;   // focal_map = f0 - neg_g + pos_g
        }

        if (c == 0) {  // IoU term: once per cell
            const float4 r = *(const float4*)(regr + pidx * 4);
            const float sx = ((float)px + 0.5f) * stride;
            const float sy = ((float)py + 0.5f) * stride;
            const float tl = fmaxf(sx - b0, 0.0f) * inv4s;
            const float tt = fmaxf(sy - b1, 0.0f) * inv4s;
            const float tr = fmaxf(b2 - sx, 0.0f) * inv4s;
            const float tb = fmaxf(b3 - sy, 0.0f) * inv4s;
            const float pl = r.x, pt = r.y, pr = r.z, pb = r.w;
            const float t_area = (tl + tr) * (tt + tb);
            const float p_area = (pl + pr) * (pt + pb);
            const float w_i = fminf(pl, tl) + fminf(pr, tr);
            const float h_i = fminf(pb, tb) + fminf(pt, tt);
            const float a_i = w_i * h_i;
            const float a_u = t_area + p_area - a_i;
            acc += -logf((a_i + 1e-7f) / (a_u + 1e-7f));
        }
    }

    // block reduction (128 threads = 4 warps)
    acc = warp_reduce(acc);
    __shared__ float sh[4];
    if ((threadIdx.x & 31) == 0) sh[threadIdx.x >> 5] = acc;
    __syncthreads();
    if (threadIdx.x == 0) {
        const float total = sh[0] + sh[1] + sh[2] + sh[3];
        g_losses[unit] = total / (float)ncells;
    }
}

// 512 threads: validity + first-minimum argmin (matches jnp.argmin tie rule).
// Output written as FLOAT32 — the harness's __output__ dtype is float
// (int -1 bit-pattern read as float is NaN, which explained rel_err=nan).
__global__ void argmin_kernel(const float* __restrict__ gt, float* __restrict__ out)
{
    const int i = blockIdx.x * blockDim.x + threadIdx.x;
    if (i >= NBG) return;
    const float* bx = gt + i * 5;
    if (fabsf(bx[0]) + fabsf(bx[1]) + fabsf(bx[2]) + fabsf(bx[3]) == 0.0f) {
        out[i] = -1.0f;
        return;
    }
    float best = g_losses[i * NLEV];
    int bl = 0;
    #pragma unroll
    for (int l = 1; l < NLEV; l++) {
        const float v = g_losses[i * NLEV + l];
        if (v < best) { best = v; bl = l; }
    }
    out[i] = (float)bl;
}

extern "C" void kernel_launch(void* const* d_in, const int* in_sizes, int n_in,
                              void* d_out, int out_size)
{
    // Resolve inputs by UNIQUE element counts — robust to metadata ordering.
    //   cls_pred:       8*21824*80 = 13,967,360
    //   regr_pred:      8*21824*4  =    698,368
    //   gt_boxes:       8*64*5     =      2,560
    //   feature_shapes: 5*2        =         10 (unused; constants hardcoded)
    const float* cls  = nullptr;
    const float* regr = nullptr;
    const float* gt   = nullptr;
    for (int i = 0; i < n_in; i++) {
        const int sz = in_sizes[i];
        if      (sz == B * TOTAL * C) cls  = (const float*)d_in[i];
        else if (sz == B * TOTAL * 4) regr = (const float*)d_in[i];
        else if (sz == B * G * 5)     gt   = (const float*)d_in[i];
    }
    float* out = (float*)d_out;
    if (!cls || !regr || !gt) return;  // should not happen

    level_loss_kernel<<<NBG * NLEV, 128>>>(cls, regr, gt);
    argmin_kernel<<<(NBG + 255) / 256, 256>>>(gt, out);
}

// round 6
// speedup vs baseline: 1.4040x; 1.4040x over previous
#include <cuda_runtime.h>

// Problem constants (fixed by setup_inputs)
#define B       8
#define G       64
#define C       80
#define NLEV    5
#define TOTAL   21824   // 128^2 + 64^2 + 32^2 + 16^2 + 8^2
#define NBG     (B * G)
#define NTHR    160     // 2 cells x 80 classes per iteration

// Scratch (device globals — no allocation). g_cnt is zero-initialized at module
// load and self-reset to 0 by the finishing block each launch (graph-replay safe).
__device__ float g_losses[NBG * NLEV];
__device__ int   g_cnt[NBG];

__device__ __forceinline__ float warp_reduce(float v) {
    #pragma unroll
    for (int o = 16; o > 0; o >>= 1)
        v += __shfl_down_sync(0xffffffffu, v, o);
    return v;
}

// One block per (bg, level). Computes loss_cls + loss_iou over the projected
// shrunk-box mask; the last of the 5 level-blocks per bg does the argmin.
__global__ __launch_bounds__(NTHR) void fused_loss_kernel(
    const float* __restrict__ cls,    // (B, TOTAL, C)
    const float* __restrict__ regr,   // (B, TOTAL, 4)
    const float* __restrict__ gt,     // (B, G, 5)
    float* __restrict__ out)          // (NBG,) float levels
{
    const int   fw_tab[NLEV]     = {128, 64, 32, 16, 8};
    const int   start_tab[NLEV]  = {0, 16384, 20480, 21504, 21760};
    const float stride_tab[NLEV] = {8.f, 16.f, 32.f, 64.f, 128.f};

    const int unit  = blockIdx.x;       // bg*5 + level
    const int level = unit % NLEV;
    const int bg    = unit / NLEV;
    const int b     = bg >> 6;          // /G
    const int tid   = threadIdx.x;

    const float* bx = gt + bg * 5;
    const float b0 = bx[0], b1 = bx[1], b2 = bx[2], b3 = bx[3];

    // invalid (zeroed) box: level-0 block writes -1, nothing else to do
    if (fabsf(b0) + fabsf(b1) + fabsf(b2) + fabsf(b3) == 0.0f) {
        if (level == 0 && tid == 0) out[bg] = -1.0f;
        return;
    }

    int label = (int)bx[4];
    label = min(max(label, 0), C - 1);

    const float stride = stride_tab[level];
    const int   fw     = fw_tab[level];
    const int   fh     = fw;
    const int   start  = start_tab[level];

    // projection — replicate reference op order exactly (stride is 2^k → exact)
    const float cx = (b0 + b2) * 0.5f;
    const float cy = (b1 + b3) * 0.5f;
    const float hw = (b2 - b0) * 0.5f * 0.2f;
    const float hh = (b3 - b1) * 0.5f * 0.2f;

    const int x1 = min(max((int)floorf((cx - hw) / stride), 0), fw - 1);
    const int y1 = min(max((int)floorf((cy - hh) / stride), 0), fh - 1);
    const int x2 = min(max((int)ceilf((cx + hw) / stride), 1), fw);
    const int y2 = min(max((int)ceilf((cy + hh) / stride), 1), fh);

    const bool empty  = (x1 == x2) | (y1 == y2);
    const int  wid    = x2 - x1;
    const int  ncells = wid * (y2 - y1);

    const long long base_b = (long long)b * TOTAL;
    const float inv4s = 1.0f / (4.0f * stride);

    float acc = 0.0f;

    if (!empty) {
        // ---- Phase 1: focal term. Thread owns fixed class c, walks cells. ----
        const int grp = tid / 80;         // 0 or 1 (const divisor)
        const int c   = tid - grp * 80;
        const bool is_label = (c == label);

        int cell = grp;
        if (cell < ncells) {
            int py = y1 + cell / wid;
            int px = x1 + cell - (cell / wid) * wid;
            for (; cell < ncells; cell += 2) {
                const long long pidx = base_b + (start + py * fw + px);
                float p = __ldg(cls + pidx * C + c);
                p = fminf(fmaxf(p, 1e-7f), 1.0f - 1e-7f);
                const float neg = 0.75f * p * p * (-log1pf(-p));   // GAMMA=2
                acc += neg;
                if (is_label) {
                    const float omp = 1.0f - p;
                    acc += 0.25f * omp * omp * (-logf(p)) - neg;   // f0 - neg_g + pos_g
                }
                px += 2;
                while (px >= x2) { px -= wid; py++; }
            }
        }

        // ---- Phase 2: IoU term, cells spread over all threads (<=1 iter) ----
        for (int cl = tid; cl < ncells; cl += NTHR) {
            const int py = y1 + cl / wid;
            const int px = x1 + cl - (cl / wid) * wid;
            const long long pidx = base_b + (start + py * fw + px);
            const float4 r = *(const float4*)(regr + pidx * 4);
            const float sx = ((float)px + 0.5f) * stride;
            const float sy = ((float)py + 0.5f) * stride;
            const float tl = fmaxf(sx - b0, 0.0f) * inv4s;
            const float tt = fmaxf(sy - b1, 0.0f) * inv4s;
            const float tr = fmaxf(b2 - sx, 0.0f) * inv4s;
            const float tb = fmaxf(b3 - sy, 0.0f) * inv4s;
            const float t_area = (tl + tr) * (tt + tb);
            const float p_area = (r.x + r.z) * (r.y + r.w);
            const float w_i = fminf(r.x, tl) + fminf(r.z, tr);
            const float h_i = fminf(r.w, tb) + fminf(r.y, tt);
            const float a_i = w_i * h_i;
            const float a_u = t_area + p_area - a_i;
            acc += -logf((a_i + 1e-7f) / (a_u + 1e-7f));
        }
    }

    // ---- Block reduction (160 threads = 5 warps) ----
    acc = warp_reduce(acc);
    __shared__ float sh[5];
    if ((tid & 31) == 0) sh[tid >> 5] = acc;
    __syncthreads();

    if (tid == 0) {
        float loss;
        if (empty) {
            loss = 1e7f;  // BIG
        } else {
            loss = (sh[0] + sh[1] + sh[2] + sh[3] + sh[4]) / (float)ncells;
        }
        g_losses[unit] = loss;
        __threadfence();                       // publish loss before arrival
        const int old = atomicAdd(&g_cnt[bg], 1);
        if (old == NLEV - 1) {                 // last of the 5 level-blocks
            __threadfence();                   // acquire: see peers' losses
            float best = __ldcg(&g_losses[bg * NLEV]);
            int   bl   = 0;
            #pragma unroll
            for (int l = 1; l < NLEV; l++) {
                const float v = __ldcg(&g_losses[bg * NLEV + l]);
                if (v < best) { best = v; bl = l; }   // first-min (jnp.argmin)
            }
            out[bg] = (float)bl;
            g_cnt[bg] = 0;                     // self-reset for next graph replay
        }
    }
}

extern "C" void kernel_launch(void* const* d_in, const int* in_sizes, int n_in,
                              void* d_out, int out_size)
{
    // Resolve inputs by UNIQUE element counts — robust to metadata ordering.
    const float* cls  = nullptr;
    const float* regr = nullptr;
    const float* gt   = nullptr;
    for (int i = 0; i < n_in; i++) {
        const int sz = in_sizes[i];
        if      (sz == B * TOTAL * C) cls  = (const float*)d_in[i];
        else if (sz == B * TOTAL * 4) regr = (const float*)d_in[i];
        else if (sz == B * G * 5)     gt   = (const float*)d_in[i];
    }
    float* out = (float*)d_out;
    if (!cls || !regr || !gt) return;

    fused_loss_kernel<<<NBG * NLEV, NTHR>>>(cls, regr, gt, out);
}

// round 8
// speedup vs baseline: 1.5771x; 1.1233x over previous
#include <cuda_runtime.h>

// Problem constants (fixed by setup_inputs)
#define B       8
#define G       64
#define C       80
#define NLEV    5
#define TOTAL   21824   // 128^2 + 64^2 + 32^2 + 16^2 + 8^2
#define NBG     (B * G)
#define NTHR    160     // 2 cells x 80 classes per iteration
#define NSUB    8       // 4 chunks of level 0 + levels 1..4

// Scratch (device globals — no allocation). g_cnt zero-initialized at load and
// self-reset by the finishing block each launch (graph-replay safe).
__device__ float g_partial[NBG * NSUB];
__device__ int   g_cnt[NBG];

__device__ __forceinline__ float warp_reduce(float v) {
    #pragma unroll
    for (int o = 16; o > 0; o >>= 1)
        v += __shfl_down_sync(0xffffffffu, v, o);
    return v;
}

// Projection per reference op order (stride = 2^k → exact division).
__device__ __forceinline__ void project(
    float b0, float b1, float b2, float b3, float stride, int fw,
    int& x1, int& y1, int& x2, int& y2)
{
    const float cx = (b0 + b2) * 0.5f;
    const float cy = (b1 + b3) * 0.5f;
    const float hw = (b2 - b0) * 0.5f * 0.2f;
    const float hh = (b3 - b1) * 0.5f * 0.2f;
    x1 = min(max((int)floorf((cx - hw) / stride), 0), fw - 1);
    y1 = min(max((int)floorf((cy - hh) / stride), 0), fw - 1);
    x2 = min(max((int)ceilf((cx + hw) / stride), 1), fw);
    y2 = min(max((int)ceilf((cy + hh) / stride), 1), fw);
}

__constant__ int   c_fw[NLEV]     = {128, 64, 32, 16, 8};
__constant__ int   c_start[NLEV]  = {0, 16384, 20480, 21504, 21760};
__constant__ float c_stride[NLEV] = {8.f, 16.f, 32.f, 64.f, 128.f};

// 8 blocks per (b,g): subs 0..3 = level-0 cell chunks, subs 4..7 = levels 1..4.
// The 8th arriving block combines partials (fixed order) and writes the argmin.
__global__ __launch_bounds__(NTHR) void fused_loss_kernel(
    const float* __restrict__ cls,    // (B, TOTAL, C)
    const float* __restrict__ regr,   // (B, TOTAL, 4)
    const float* __restrict__ gt,     // (B, G, 5)
    float* __restrict__ out)          // (NBG,) float levels
{
    const int uid   = blockIdx.x;
    const int bg    = uid >> 3;
    const int sub   = uid & 7;
    const int level = (sub < 4) ? 0 : (sub - 3);
    const int chunk = (sub < 4) ? sub : 0;
    const int nch   = (sub < 4) ? 4 : 1;
    const int b     = bg >> 6;          // /G
    const int tid   = threadIdx.x;

    const float* bx = gt + bg * 5;
    const float b0 = bx[0], b1 = bx[1], b2 = bx[2], b3 = bx[3];

    // invalid (zeroed) box: one block writes -1, nothing else to do
    if (fabsf(b0) + fabsf(b1) + fabsf(b2) + fabsf(b3) == 0.0f) {
        if (sub == 0 && tid == 0) out[bg] = -1.0f;
        return;
    }

    int label = (int)bx[4];
    label = min(max(label, 0), C - 1);

    const float stride = c_stride[level];
    const int   fw     = c_fw[level];
    const int   start  = c_start[level];

    int x1, y1, x2, y2;
    project(b0, b1, b2, b3, stride, fw, x1, y1, x2, y2);

    const bool empty  = (x1 == x2) | (y1 == y2);
    const int  wid    = x2 - x1;
    const int  ncells = empty ? 0 : wid * (y2 - y1);

    // this block's cell range
    const int lo = (ncells * chunk) / nch;
    const int hi = (ncells * (chunk + 1)) / nch;

    const long long base_b = (long long)b * TOTAL;
    const float inv4s = 1.0f / (4.0f * stride);

    float acc = 0.0f;

    if (lo < hi) {
        // ---- Phase 1: focal term. Thread owns fixed class c, walks cells. ----
        const int grp = tid / 80;         // 0 or 1 (const divisor)
        const int c   = tid - grp * 80;
        const bool is_label = (c == label);

        int cell = lo + grp;
        if (cell < hi) {
            int py = y1 + cell / wid;
            int px = x1 + cell - (cell / wid) * wid;
            for (; cell < hi; cell += 2) {
                const long long pidx = base_b + (start + py * fw + px);
                float p = __ldg(cls + pidx * C + c);
                p = fminf(fmaxf(p, 1e-7f), 1.0f - 1e-7f);
                const float neg = 0.75f * p * p * (-log1pf(-p));   // GAMMA=2
                acc += neg;
                if (is_label) {
                    const float omp = 1.0f - p;
                    acc += 0.25f * omp * omp * (-logf(p)) - neg;   // f0 - neg_g + pos_g
                }
                px += 2;
                while (px >= x2) { px -= wid; py++; }
            }
        }

        // ---- Phase 2: IoU term, cells spread over all threads (<=1 iter) ----
        for (int cl = lo + tid; cl < hi; cl += NTHR) {
            const int py = y1 + cl / wid;
            const int px = x1 + cl - (cl / wid) * wid;
            const long long pidx = base_b + (start + py * fw + px);
            const float4 r = *(const float4*)(regr + pidx * 4);
            const float sx = ((float)px + 0.5f) * stride;
            const float sy = ((float)py + 0.5f) * stride;
            const float tl = fmaxf(sx - b0, 0.0f) * inv4s;
            const float tt = fmaxf(sy - b1, 0.0f) * inv4s;
            const float tr = fmaxf(b2 - sx, 0.0f) * inv4s;
            const float tb = fmaxf(b3 - sy, 0.0f) * inv4s;
            const float t_area = (tl + tr) * (tt + tb);
            const float p_area = (r.x + r.z) * (r.y + r.w);
            const float w_i = fminf(r.x, tl) + fminf(r.z, tr);
            const float h_i = fminf(r.w, tb) + fminf(r.y, tt);
            const float a_i = w_i * h_i;
            const float a_u = t_area + p_area - a_i;
            acc += -logf((a_i + 1e-7f) / (a_u + 1e-7f));
        }
    }

    // ---- Block reduction (160 threads = 5 warps) ----
    acc = warp_reduce(acc);
    __shared__ float sh[5];
    if ((tid & 31) == 0) sh[tid >> 5] = acc;
    __syncthreads();

    if (tid == 0) {
        g_partial[uid] = sh[0] + sh[1] + sh[2] + sh[3] + sh[4];
        __threadfence();                       // publish partial before arrival
        const int old = atomicAdd(&g_cnt[bg], 1);
        if (old == NSUB - 1) {                 // last of the 8 blocks for this bg
            __threadfence();                   // acquire: see peers' partials
            const float* gp = &g_partial[bg * NSUB];

            float best = 3.0e38f;
            int   bl   = 0;
            #pragma unroll
            for (int l = 0; l < NLEV; l++) {
                int lx1, ly1, lx2, ly2;
                project(b0, b1, b2, b3, c_stride[l], c_fw[l], lx1, ly1, lx2, ly2);
                float loss;
                if ((lx1 == lx2) | (ly1 == ly2)) {
                    loss = 1e7f;               // BIG
                } else {
                    const int nc = (lx2 - lx1) * (ly2 - ly1);
                    float s;
                    if (l == 0)                // fixed summation order: chunks 0..3
                        s = ((__ldcg(gp + 0) + __ldcg(gp + 1))
                           + (__ldcg(gp + 2) + __ldcg(gp + 3)));
                    else
                        s = __ldcg(gp + 3 + l);
                    loss = s / (float)nc;
                }
                if (loss < best) { best = loss; bl = l; }   // first-min (jnp.argmin)
            }
            out[bg] = (float)bl;
            g_cnt[bg] = 0;                     // self-reset for next graph replay
        }
    }
}

extern "C" void kernel_launch(void* const* d_in, const int* in_sizes, int n_in,
                              void* d_out, int out_size)
{
    // Resolve inputs by UNIQUE element counts — robust to metadata ordering.
    const float* cls  = nullptr;
    const float* regr = nullptr;
    const float* gt   = nullptr;
    for (int i = 0; i < n_in; i++) {
        const int sz = in_sizes[i];
        if      (sz == B * TOTAL * C) cls  = (const float*)d_in[i];
        else if (sz == B * TOTAL * 4) regr = (const float*)d_in[i];
        else if (sz == B * G * 5)     gt   = (const float*)d_in[i];
    }
    float* out = (float*)d_out;
    if (!cls || !regr || !gt) return;

    fused_loss_kernel<<<NBG * NSUB, NTHR>>>(cls, regr, gt, out);
}